// round 6
// baseline (speedup 1.0000x reference)
#include <cuda_runtime.h>
#include <cuda_fp16.h>
#include <stdint.h>
#include <math.h>

// ---------------------------------------------------------------------------
// Problem constants
// ---------------------------------------------------------------------------
#define BB 4
#define SS 2048
#define MM 1024
#define FF 4096
static const long SMTOT = (long)SS * MM;
static const long SM4   = SMTOT / 4;

// ---------------------------------------------------------------------------
// Scratch (device globals)
// ---------------------------------------------------------------------------
__device__ float  g_pre1  [(long)BB * SS * MM];
__device__ float  g_h     [(long)BB * SS * MM];
__device__ float  g_pre2  [(long)BB * SS * MM];
__device__ float  g_part  [BB * 256 * 2];
__device__ float  g_stats [BB * 2];

__device__ __half g_x16   [(long)BB * SS * MM];   // 16 MB
__device__ __half g_xt16  [(long)BB * SS * MM];   // 16 MB  [B,M,S]
__device__ __half g_attn16[(long)BB * SS * SS];   // 32 MB (scores then attn, in place)
__device__ __half g_ctx16 [(long)BB * SS * MM];   // 16 MB
__device__ __half g_h16   [(long)BB * SS * MM];   // 16 MB
__device__ __half g_ff116 [(long)BB * SS * FF];   // 64 MB
__device__ __half g_wout16[(long)MM * MM];
__device__ __half g_w116  [(long)FF * MM];
__device__ __half g_w216  [(long)MM * FF];

// ---------------------------------------------------------------------------
// helpers
// ---------------------------------------------------------------------------
static __device__ __forceinline__ uint32_t smem_u32(const void* p) {
    uint32_t a;
    asm("{ .reg .u64 t; cvta.to.shared.u64 t, %1; cvt.u32.u64 %0, t; }"
        : "=r"(a) : "l"(p));
    return a;
}

static __device__ __forceinline__ void cp16(uint32_t saddr, const void* gaddr) {
    asm volatile("cp.async.cg.shared.global [%0], [%1], 16;"
                 :: "r"(saddr), "l"(gaddr) : "memory");
}
static __device__ __forceinline__ void cp_commit() {
    asm volatile("cp.async.commit_group;" ::: "memory");
}
template<int N>
static __device__ __forceinline__ void cp_wait() {
    asm volatile("cp.async.wait_group %0;" :: "n"(N) : "memory");
}

static __device__ __forceinline__ void ldsm4(uint32_t* r, uint32_t addr) {
    asm volatile("ldmatrix.sync.aligned.m8n8.x4.shared.b16 {%0,%1,%2,%3}, [%4];"
                 : "=r"(r[0]), "=r"(r[1]), "=r"(r[2]), "=r"(r[3]) : "r"(addr));
}

static __device__ __forceinline__ void mma_f16(
    float& c0, float& c1, float& c2, float& c3,
    uint32_t a0, uint32_t a1, uint32_t a2, uint32_t a3,
    uint32_t b0, uint32_t b1)
{
    asm volatile(
        "mma.sync.aligned.m16n8k16.row.col.f32.f16.f16.f32 "
        "{%0,%1,%2,%3}, {%4,%5,%6,%7}, {%8,%9}, {%0,%1,%2,%3};"
        : "+f"(c0), "+f"(c1), "+f"(c2), "+f"(c3)
        : "r"(a0), "r"(a1), "r"(a2), "r"(a3), "r"(b0), "r"(b1));
}

// ---------------------------------------------------------------------------
// fp16 NT GEMM, cp.async 3-stage pipeline:
//   C[m,n] = epi( sum_k A[m,k]*B[n,k] ),  A:[M,K] f16, B:[N,K] f16 row-major.
// BM=128, BN=256, BK=64; 256 threads (8 warps: 2 m x 4 n); warp tile 64x64.
// Smem rows = 128 B, SW128 swizzle (16B unit ^= row&7). One barrier per stage.
// EPI: 0=*alpha  1=plain  2=+R  3=relu+bias  4=+bias+R ; OT = float | __half
// ---------------------------------------------------------------------------
#define STAGES     3
#define A_BYTES    16384                    // 128 rows * 128 B
#define B_BYTES    32768                    // 256 rows * 128 B
#define STAGE_B    (A_BYTES + B_BYTES)      // 49152
#define SMEM_TOT   (STAGES * STAGE_B)       // 147456

template<int EPI, typename OT>
__global__ __launch_bounds__(256)
void gemm_h16(const __half* __restrict__ A, const __half* __restrict__ Bm,
              OT* __restrict__ C, const float* __restrict__ bias,
              const float* __restrict__ R,
              int Kdim, int Ndim, long sA, long sB, long sC, float alpha)
{
    extern __shared__ __align__(1024) char sm[];
    const uint32_t smb = smem_u32(sm);

    const int tid  = threadIdx.x;
    const int wid  = tid >> 5;
    const int lane = tid & 31;
    const int gid  = lane >> 2;
    const int lq   = lane & 3;
    const int wm   = wid >> 2;      // 0..1
    const int wn   = wid & 3;       // 0..3

    const long bz = blockIdx.z;
    const int  m0 = blockIdx.y * 128;
    const int  n0 = blockIdx.x * 256;

    // ---- cp.async loader mapping
    // A: thread pair covers one row: lr = tid>>1 (0..127), units lu..lu+3
    // B: thread covers one row: br = tid (0..255), units 0..7
    const int lr   = tid >> 1;
    const int lu   = (tid & 1) * 4;
    const int lswz = lr & 7;
    const int bswz = tid & 7;
    const char* Agb = (const char*)(A  + bz * sA + (long)(m0 + lr)  * Kdim);
    const char* Bgb = (const char*)(Bm + bz * sB + (long)(n0 + tid) * Kdim);
    const uint32_t sArow = lr * 128;
    const uint32_t sBrow = tid * 128;

    // ---- ldmatrix addressing
    const int g8   = lane >> 3;
    const int r8   = lane & 7;
    const int ro8  = (g8 & 1) * 8;
    const int cbit = g8 >> 1;           // 16B unit parity within k16

    uint32_t aRowOff[4]; int aSwz[4];
    #pragma unroll
    for (int mt = 0; mt < 4; mt++) {
        int r = wm * 64 + mt * 16 + ro8 + r8;
        aRowOff[mt] = r * 128;
        aSwz[mt] = r & 7;
    }
    uint32_t bRowOff[4]; int bSwz[4];
    #pragma unroll
    for (int p = 0; p < 4; p++) {
        int r = wn * 64 + p * 16 + ro8 + r8;
        bRowOff[p] = r * 128;
        bSwz[p] = r & 7;
    }

    float acc[4][8][4];
    #pragma unroll
    for (int i = 0; i < 4; i++)
        #pragma unroll
        for (int j = 0; j < 8; j++)
            #pragma unroll
            for (int q = 0; q < 4; q++) acc[i][j][q] = 0.f;

    const int KT = Kdim >> 6;   // BK=64

    auto load_stage = [&](int s, int kt) {
        const uint32_t sa = smb + s * STAGE_B + sArow;
        const uint32_t sb = smb + s * STAGE_B + A_BYTES + sBrow;
        const long gk = (long)kt * 128;   // bytes along K
        #pragma unroll
        for (int i = 0; i < 4; i++) {
            const int u = lu + i;
            cp16(sa + ((u ^ lswz) << 4), Agb + gk + u * 16);
        }
        #pragma unroll
        for (int u = 0; u < 8; u++) {
            cp16(sb + ((u ^ bswz) << 4), Bgb + gk + u * 16);
        }
    };

    load_stage(0, 0); cp_commit();
    if (KT > 1) load_stage(1, 1);
    cp_commit();

    for (int kt = 0; kt < KT; kt++) {
        const int s = kt % 3;
        cp_wait<1>();
        __syncthreads();          // single barrier per stage (see ring proof)
        if (kt + 2 < KT) load_stage((kt + 2) % 3, kt + 2);
        cp_commit();

        const uint32_t aBase = smb + s * STAGE_B;
        const uint32_t bBase = aBase + A_BYTES;
        #pragma unroll
        for (int ks = 0; ks < 4; ks++) {
            const int u = ks * 2 + cbit;
            uint32_t af[4][4];
            #pragma unroll
            for (int mt = 0; mt < 4; mt++)
                ldsm4(af[mt], aBase + aRowOff[mt] + ((u ^ aSwz[mt]) << 4));
            uint32_t bf[4][4];
            #pragma unroll
            for (int p = 0; p < 4; p++)
                ldsm4(bf[p], bBase + bRowOff[p] + ((u ^ bSwz[p]) << 4));
            #pragma unroll
            for (int mt = 0; mt < 4; mt++)
                #pragma unroll
                for (int nt = 0; nt < 8; nt++) {
                    const int pr = nt >> 1, od = nt & 1;
                    mma_f16(acc[mt][nt][0], acc[mt][nt][1],
                            acc[mt][nt][2], acc[mt][nt][3],
                            af[mt][0], af[mt][1], af[mt][2], af[mt][3],
                            bf[pr][od], bf[pr][od + 2]);
                }
        }
    }

    // ---------------- epilogue ----------------
    OT* Cb = C + bz * sC;
    #pragma unroll
    for (int mt = 0; mt < 4; mt++) {
        const long row0 = m0 + wm * 64 + mt * 16 + gid;
        #pragma unroll
        for (int nt = 0; nt < 8; nt++) {
            const long col = n0 + wn * 64 + nt * 8 + lq * 2;
            float v0 = acc[mt][nt][0], v1 = acc[mt][nt][1];
            float v2 = acc[mt][nt][2], v3 = acc[mt][nt][3];
            if (EPI == 0) { v0 *= alpha; v1 *= alpha; v2 *= alpha; v3 *= alpha; }
            if (EPI == 3 || EPI == 4) {
                float2 b2 = *(const float2*)(bias + col);
                v0 += b2.x; v1 += b2.y; v2 += b2.x; v3 += b2.y;
            }
            if (EPI == 3) {
                v0 = fmaxf(v0, 0.f); v1 = fmaxf(v1, 0.f);
                v2 = fmaxf(v2, 0.f); v3 = fmaxf(v3, 0.f);
            }
            const long o0 = row0 * (long)Ndim + col;
            const long o1 = (row0 + 8) * (long)Ndim + col;
            if (EPI == 2 || EPI == 4) {
                float2 r0 = *(const float2*)(R + o0);
                float2 r1 = *(const float2*)(R + o1);
                v0 += r0.x; v1 += r0.y; v2 += r1.x; v3 += r1.y;
            }
            if (sizeof(OT) == 4) {
                *(float2*)((float*)Cb + o0) = make_float2(v0, v1);
                *(float2*)((float*)Cb + o1) = make_float2(v2, v3);
            } else {
                *(__half2*)((__half*)Cb + o0) = __floats2half2_rn(v0, v1);
                *(__half2*)((__half*)Cb + o1) = __floats2half2_rn(v2, v3);
            }
        }
    }
}

// ---------------------------------------------------------------------------
// f32 -> f16 elementwise convert
// ---------------------------------------------------------------------------
__global__ __launch_bounds__(256)
void cvt16_k(const float* __restrict__ in, __half* __restrict__ out, long n4)
{
    long i = (long)blockIdx.x * 256 + threadIdx.x;
    if (i >= n4) return;
    float4 v = ((const float4*)in)[i];
    ((__half2*)out)[i * 2]     = __floats2half2_rn(v.x, v.y);
    ((__half2*)out)[i * 2 + 1] = __floats2half2_rn(v.z, v.w);
}

// ---------------------------------------------------------------------------
// Transpose per batch to fp16: xt16[b][m][s] = x[b][s][m]
// ---------------------------------------------------------------------------
__global__ __launch_bounds__(256)
void transpose16_k(const float* __restrict__ x, __half* __restrict__ xt)
{
    __shared__ float t[32][33];
    const int b  = blockIdx.z;
    const int bx = blockIdx.x * 32;
    const int by = blockIdx.y * 32;
    const float* xp = x  + (long)b * SMTOT;
    __half*      yp = xt + (long)b * SMTOT;
    const int txx = threadIdx.x, tyy = threadIdx.y;
    #pragma unroll
    for (int i = 0; i < 4; i++)
        t[tyy + i * 8][txx] = xp[(long)(by + tyy + i * 8) * MM + bx + txx];
    __syncthreads();
    #pragma unroll
    for (int i = 0; i < 4; i++)
        yp[(long)(bx + tyy + i * 8) * SS + by + txx] = __float2half(t[txx][tyy + i * 8]);
}

// ---------------------------------------------------------------------------
// Row softmax over 2048 columns, fp16 in / fp16 out, IN PLACE (one block/row)
// ---------------------------------------------------------------------------
__global__ __launch_bounds__(256)
void softmax16_k(__half* __restrict__ data)
{
    long row = blockIdx.x;
    __half2* p = (__half2*)(data + row * (long)SS);
    int t = threadIdx.x;
    float2 v[4];
    float mx = -INFINITY;
    #pragma unroll
    for (int i = 0; i < 4; i++) {
        __half2 h = p[t + i * 256];
        v[i] = __half22float2(h);
        mx = fmaxf(mx, fmaxf(v[i].x, v[i].y));
    }
    __shared__ float red[256];
    red[t] = mx; __syncthreads();
    for (int s = 128; s > 0; s >>= 1) {
        if (t < s) red[t] = fmaxf(red[t], red[t + s]);
        __syncthreads();
    }
    mx = red[0];
    __syncthreads();
    float sum = 0.f;
    #pragma unroll
    for (int i = 0; i < 4; i++) {
        v[i].x = __expf(v[i].x - mx);
        v[i].y = __expf(v[i].y - mx);
        sum += v[i].x + v[i].y;
    }
    red[t] = sum; __syncthreads();
    for (int s = 128; s > 0; s >>= 1) {
        if (t < s) red[t] += red[t + s];
        __syncthreads();
    }
    float inv = 1.f / red[0];
    #pragma unroll
    for (int i = 0; i < 4; i++)
        p[t + i * 256] = __floats2half2_rn(v[i].x * inv, v[i].y * inv);
}

// ---------------------------------------------------------------------------
// LayerNorm over full (S,M) plane per batch — deterministic 3-stage
// ---------------------------------------------------------------------------
__global__ __launch_bounds__(256)
void ln_reduce_k(const float* __restrict__ xx, float* __restrict__ part)
{
    int b = blockIdx.y;
    const float4* p = (const float4*)(xx + (long)b * SMTOT) + (long)blockIdx.x * 2048;
    float s = 0.f, q = 0.f;
    for (int i = threadIdx.x; i < 2048; i += 256) {
        float4 v = p[i];
        s += v.x + v.y + v.z + v.w;
        q += v.x * v.x + v.y * v.y + v.z * v.z + v.w * v.w;
    }
    __shared__ float rs[256], rq[256];
    rs[threadIdx.x] = s; rq[threadIdx.x] = q; __syncthreads();
    for (int st = 128; st > 0; st >>= 1) {
        if (threadIdx.x < st) {
            rs[threadIdx.x] += rs[threadIdx.x + st];
            rq[threadIdx.x] += rq[threadIdx.x + st];
        }
        __syncthreads();
    }
    if (threadIdx.x == 0) {
        int idx = (b * 256 + blockIdx.x) * 2;
        part[idx]     = rs[0];
        part[idx + 1] = rq[0];
    }
}

__global__ __launch_bounds__(256)
void ln_finalize_k(const float* __restrict__ part, float* __restrict__ stats)
{
    int b = blockIdx.x, t = threadIdx.x;
    float s = part[(b * 256 + t) * 2];
    float q = part[(b * 256 + t) * 2 + 1];
    __shared__ float rs[256], rq[256];
    rs[t] = s; rq[t] = q; __syncthreads();
    for (int st = 128; st > 0; st >>= 1) {
        if (t < st) { rs[t] += rs[t + st]; rq[t] += rq[t + st]; }
        __syncthreads();
    }
    if (t == 0) {
        float mean = rs[0] / (float)SMTOT;
        float var  = rq[0] / (float)SMTOT - mean * mean;
        stats[b * 2]     = mean;
        stats[b * 2 + 1] = rsqrtf(var + 1e-5f);
    }
}

template<bool WH>
__global__ __launch_bounds__(256)
void ln_apply_k(const float* __restrict__ xx, const float* __restrict__ w,
                const float* __restrict__ bbp, const float* __restrict__ stats,
                float* __restrict__ y, __half* __restrict__ y16)
{
    long i = (long)blockIdx.x * 256 + threadIdx.x;
    int b  = (int)(i / SM4);
    long sm = i - (long)b * SM4;
    float mean = stats[b * 2];
    float rstd = stats[b * 2 + 1];
    float4 v  = ((const float4*)xx)[i];
    float4 wv = ((const float4*)w)[sm];
    float4 bv = ((const float4*)bbp)[sm];
    float4 o;
    o.x = (v.x - mean) * rstd * wv.x + bv.x;
    o.y = (v.y - mean) * rstd * wv.y + bv.y;
    o.z = (v.z - mean) * rstd * wv.z + bv.z;
    o.w = (v.w - mean) * rstd * wv.w + bv.w;
    ((float4*)y)[i] = o;
    if (WH) {
        ((__half2*)y16)[i * 2]     = __floats2half2_rn(o.x, o.y);
        ((__half2*)y16)[i * 2 + 1] = __floats2half2_rn(o.z, o.w);
    }
}

// ---------------------------------------------------------------------------
// Launch
// ---------------------------------------------------------------------------
extern "C" void kernel_launch(void* const* d_in, const int* in_sizes, int n_in,
                              void* d_out, int out_size)
{
    const float* x     = (const float*)d_in[0];
    const float* w_out = (const float*)d_in[1];
    const float* ln1_w = (const float*)d_in[2];
    const float* ln1_b = (const float*)d_in[3];
    const float* w1    = (const float*)d_in[4];
    const float* b1    = (const float*)d_in[5];
    const float* w2    = (const float*)d_in[6];
    const float* b2    = (const float*)d_in[7];
    const float* ln2_w = (const float*)d_in[8];
    const float* ln2_b = (const float*)d_in[9];
    float* out = (float*)d_out;

    float  *pre1, *h, *pre2, *part, *stats;
    __half *x16, *xt16, *attn16, *ctx16, *h16, *ff116, *wout16, *w116, *w216;
    cudaGetSymbolAddress((void**)&pre1,   g_pre1);
    cudaGetSymbolAddress((void**)&h,      g_h);
    cudaGetSymbolAddress((void**)&pre2,   g_pre2);
    cudaGetSymbolAddress((void**)&part,   g_part);
    cudaGetSymbolAddress((void**)&stats,  g_stats);
    cudaGetSymbolAddress((void**)&x16,    g_x16);
    cudaGetSymbolAddress((void**)&xt16,   g_xt16);
    cudaGetSymbolAddress((void**)&attn16, g_attn16);
    cudaGetSymbolAddress((void**)&ctx16,  g_ctx16);
    cudaGetSymbolAddress((void**)&h16,    g_h16);
    cudaGetSymbolAddress((void**)&ff116,  g_ff116);
    cudaGetSymbolAddress((void**)&wout16, g_wout16);
    cudaGetSymbolAddress((void**)&w116,   g_w116);
    cudaGetSymbolAddress((void**)&w216,   g_w216);

    cudaFuncSetAttribute(gemm_h16<0, __half>, cudaFuncAttributeMaxDynamicSharedMemorySize, SMEM_TOT);
    cudaFuncSetAttribute(gemm_h16<1, __half>, cudaFuncAttributeMaxDynamicSharedMemorySize, SMEM_TOT);
    cudaFuncSetAttribute(gemm_h16<2, float>,  cudaFuncAttributeMaxDynamicSharedMemorySize, SMEM_TOT);
    cudaFuncSetAttribute(gemm_h16<3, __half>, cudaFuncAttributeMaxDynamicSharedMemorySize, SMEM_TOT);
    cudaFuncSetAttribute(gemm_h16<4, float>,  cudaFuncAttributeMaxDynamicSharedMemorySize, SMEM_TOT);

    dim3 blk(256);
    const float scale = 1.0f / 32.0f;   // 1/sqrt(1024)
    const long SSQ = (long)SS * SS;

    // 0. conversions (independent)
    cvt16_k<<<(unsigned)((BB * SMTOT / 4) / 256), blk>>>(x, x16, BB * SMTOT / 4);
    transpose16_k<<<dim3(MM / 32, SS / 32, BB), dim3(32, 8)>>>(x, xt16);
    cvt16_k<<<(unsigned)(((long)MM * MM / 4) / 256), blk>>>(w_out, wout16, (long)MM * MM / 4);
    cvt16_k<<<(unsigned)(((long)FF * MM / 4) / 256), blk>>>(w1, w116, (long)FF * MM / 4);
    cvt16_k<<<(unsigned)(((long)MM * FF / 4) / 256), blk>>>(w2, w216, (long)MM * FF / 4);

    // 1. scores16 = (x @ x^T) * scale    per-batch NT -> f16, into attn buffer
    gemm_h16<0, __half><<<dim3(SS / 256, SS / 128, BB), blk, SMEM_TOT>>>(
        x16, x16, attn16, nullptr, nullptr, MM, SS, SMTOT, SMTOT, SSQ, scale);

    // 2. softmax rows, in place on f16
    softmax16_k<<<(unsigned)(BB * SS), blk>>>(attn16);

    // 3. ctx16 = attn @ x                per-batch NT with B = xt16
    gemm_h16<1, __half><<<dim3(MM / 256, SS / 128, BB), blk, SMEM_TOT>>>(
        attn16, xt16, ctx16, nullptr, nullptr, SS, MM, SSQ, SMTOT, SMTOT, 1.f);

    // 4. pre1 = ctx @ w_out^T + x        folded: M=8192, N=1024, K=1024
    gemm_h16<2, float><<<dim3(MM / 256, (BB * SS) / 128, 1), blk, SMEM_TOT>>>(
        ctx16, wout16, pre1, nullptr, x, MM, MM, 0, 0, 0, 1.f);

    // 5. h = LN1(pre1), h16
    ln_reduce_k<<<dim3(256, BB), blk>>>(pre1, part);
    ln_finalize_k<<<BB, blk>>>(part, stats);
    ln_apply_k<true><<<(unsigned)((BB * SMTOT / 4) / 256), blk>>>(pre1, ln1_w, ln1_b, stats, h, h16);

    // 6. ff116 = relu(h @ w1^T + b1)     folded: M=8192, N=4096, K=1024
    gemm_h16<3, __half><<<dim3(FF / 256, (BB * SS) / 128, 1), blk, SMEM_TOT>>>(
        h16, w116, ff116, b1, nullptr, MM, FF, 0, 0, 0, 1.f);

    // 7. pre2 = ff1 @ w2^T + b2 + h      folded: M=8192, N=1024, K=4096
    gemm_h16<4, float><<<dim3(MM / 256, (BB * SS) / 128, 1), blk, SMEM_TOT>>>(
        ff116, w216, pre2, b2, h, FF, MM, 0, 0, 0, 1.f);

    // 8. out = LN2(pre2)
    ln_reduce_k<<<dim3(256, BB), blk>>>(pre2, part);
    ln_finalize_k<<<BB, blk>>>(part, stats);
    ln_apply_k<false><<<(unsigned)((BB * SMTOT / 4) / 256), blk>>>(pre2, ln2_w, ln2_b, stats, out, nullptr);
}

// round 7
// speedup vs baseline: 1.2004x; 1.2004x over previous
#include <cuda_runtime.h>
#include <cuda_fp16.h>
#include <stdint.h>
#include <math.h>

// ---------------------------------------------------------------------------
// Problem constants
// ---------------------------------------------------------------------------
#define BB 4
#define SS 2048
#define MM 1024
#define FF 4096
static const long SMTOT = (long)SS * MM;
static const long SM4   = SMTOT / 4;

// ---------------------------------------------------------------------------
// Scratch (device globals)
// ---------------------------------------------------------------------------
__device__ float  g_pre1  [(long)BB * SS * MM];
__device__ float  g_h     [(long)BB * SS * MM];
__device__ float  g_pre2  [(long)BB * SS * MM];
__device__ float  g_part  [BB * 256 * 2];
__device__ float  g_stats [BB * 2];

__device__ __half g_x16   [(long)BB * SS * MM];   // 16 MB
__device__ __half g_xt16  [(long)BB * SS * MM];   // 16 MB  [B,M,S]
__device__ __half g_attn16[(long)BB * SS * SS];   // 32 MB (scores then attn, in place)
__device__ __half g_ctx16 [(long)BB * SS * MM];   // 16 MB
__device__ __half g_h16   [(long)BB * SS * MM];   // 16 MB
__device__ __half g_ff116 [(long)BB * SS * FF];   // 64 MB
__device__ __half g_wout16[(long)MM * MM];
__device__ __half g_w116  [(long)FF * MM];
__device__ __half g_w216  [(long)MM * FF];

// ---------------------------------------------------------------------------
// helpers
// ---------------------------------------------------------------------------
static __device__ __forceinline__ uint32_t smem_u32(const void* p) {
    uint32_t a;
    asm("{ .reg .u64 t; cvta.to.shared.u64 t, %1; cvt.u32.u64 %0, t; }"
        : "=r"(a) : "l"(p));
    return a;
}

static __device__ __forceinline__ void cp16(uint32_t saddr, const void* gaddr) {
    asm volatile("cp.async.cg.shared.global [%0], [%1], 16;"
                 :: "r"(saddr), "l"(gaddr) : "memory");
}
static __device__ __forceinline__ void cp_commit() {
    asm volatile("cp.async.commit_group;" ::: "memory");
}
template<int N>
static __device__ __forceinline__ void cp_wait() {
    asm volatile("cp.async.wait_group %0;" :: "n"(N) : "memory");
}

static __device__ __forceinline__ void ldsm4(uint32_t* r, uint32_t addr) {
    asm volatile("ldmatrix.sync.aligned.m8n8.x4.shared.b16 {%0,%1,%2,%3}, [%4];"
                 : "=r"(r[0]), "=r"(r[1]), "=r"(r[2]), "=r"(r[3]) : "r"(addr));
}

static __device__ __forceinline__ void mma_f16(
    float& c0, float& c1, float& c2, float& c3,
    uint32_t a0, uint32_t a1, uint32_t a2, uint32_t a3,
    uint32_t b0, uint32_t b1)
{
    asm volatile(
        "mma.sync.aligned.m16n8k16.row.col.f32.f16.f16.f32 "
        "{%0,%1,%2,%3}, {%4,%5,%6,%7}, {%8,%9}, {%0,%1,%2,%3};"
        : "+f"(c0), "+f"(c1), "+f"(c2), "+f"(c3)
        : "r"(a0), "r"(a1), "r"(a2), "r"(a3), "r"(b0), "r"(b1));
}

// ---------------------------------------------------------------------------
// fp16 NT GEMM, cp.async 3-stage pipeline (R5 geometry):
//   C[m,n] = epi( sum_k A[m,k]*B[n,k] ),  A:[M,K] f16, B:[N,K] f16 row-major.
// BM=BN=128, BK=64; 256 threads; warps 2(m) x 4(n); warp tile 64x32.
// Smem rows = 128 B, SW128 swizzle (16B unit ^= row&7). One barrier per stage.
// EPI: 0=*alpha  1=plain  2=+R  3=relu+bias  4=+bias+R ; OT = float | __half
// ---------------------------------------------------------------------------
#define STAGES     3
#define STAGE_B    32768          // 2 matrices * 128 rows * 128 B
#define SMEM_TOT   (STAGES * STAGE_B)

template<int EPI, typename OT>
__global__ __launch_bounds__(256, 2)
void gemm_h16(const __half* __restrict__ A, const __half* __restrict__ Bm,
              OT* __restrict__ C, const float* __restrict__ bias,
              const float* __restrict__ R,
              int Kdim, int Ndim, long sA, long sB, long sC, float alpha)
{
    extern __shared__ __align__(1024) char sm[];
    const uint32_t smb = smem_u32(sm);

    const int tid  = threadIdx.x;
    const int wid  = tid >> 5;
    const int lane = tid & 31;
    const int gid  = lane >> 2;
    const int lq   = lane & 3;
    const int wm   = wid >> 2;      // 0..1
    const int wn   = wid & 3;       // 0..3

    const long bz = blockIdx.z;
    const int  m0 = blockIdx.y * 128;
    const int  n0 = blockIdx.x * 128;

    // ---- cp.async loader mapping: thread -> (row, 4 consecutive 16B units)
    const int lr = tid >> 1;            // 0..127
    const int lu = (tid & 1) * 4;       // 0 or 4
    const int lswz = lr & 7;
    const char* Agb = (const char*)(A  + bz * sA + (long)(m0 + lr) * Kdim);
    const char* Bgb = (const char*)(Bm + bz * sB + (long)(n0 + lr) * Kdim);
    const uint32_t sArow = lr * 128;

    // ---- ldmatrix addressing
    const int g8  = lane >> 3;
    const int r8  = lane & 7;
    const int ro8 = (g8 & 1) * 8;
    const int cbit = g8 >> 1;           // 16B unit parity within k16

    uint32_t aRowOff[4]; int aSwz[4];
    #pragma unroll
    for (int mt = 0; mt < 4; mt++) {
        int r = wm * 64 + mt * 16 + ro8 + r8;
        aRowOff[mt] = r * 128;
        aSwz[mt] = r & 7;
    }
    uint32_t bRowOff[2]; int bSwz[2];
    #pragma unroll
    for (int p = 0; p < 2; p++) {
        int r = wn * 32 + p * 16 + ro8 + r8;
        bRowOff[p] = r * 128;
        bSwz[p] = r & 7;
    }

    float acc[4][4][4];
    #pragma unroll
    for (int i = 0; i < 4; i++)
        #pragma unroll
        for (int j = 0; j < 4; j++)
            #pragma unroll
            for (int q = 0; q < 4; q++) acc[i][j][q] = 0.f;

    const int KT = Kdim >> 6;   // BK=64

    auto load_stage = [&](int s, int kt) {
        const uint32_t sa = smb + s * STAGE_B + sArow;
        const uint32_t sb = sa + 16384;
        const long gk = (long)kt * 128;   // bytes along K
        #pragma unroll
        for (int i = 0; i < 4; i++) {
            const int u = lu + i;
            const uint32_t so = ((u ^ lswz) << 4);
            cp16(sa + so, Agb + gk + u * 16);
            cp16(sb + so, Bgb + gk + u * 16);
        }
    };

    load_stage(0, 0); cp_commit();
    if (KT > 1) load_stage(1, 1);
    cp_commit();

    for (int kt = 0; kt < KT; kt++) {
        const int s = kt % 3;
        cp_wait<1>();
        __syncthreads();   // single barrier: prefetch target (kt+2)%3==(kt-1)%3,
                           // whose consumers all passed this barrier already
        if (kt + 2 < KT) load_stage((kt + 2) % 3, kt + 2);
        cp_commit();

        const uint32_t aBase = smb + s * STAGE_B;
        const uint32_t bBase = aBase + 16384;
        #pragma unroll
        for (int ks = 0; ks < 4; ks++) {
            const int u = ks * 2 + cbit;
            uint32_t af[4][4];
            #pragma unroll
            for (int mt = 0; mt < 4; mt++)
                ldsm4(af[mt], aBase + aRowOff[mt] + ((u ^ aSwz[mt]) << 4));
            uint32_t bf[2][4];
            #pragma unroll
            for (int p = 0; p < 2; p++)
                ldsm4(bf[p], bBase + bRowOff[p] + ((u ^ bSwz[p]) << 4));
            #pragma unroll
            for (int mt = 0; mt < 4; mt++)
                #pragma unroll
                for (int nt = 0; nt < 4; nt++) {
                    const int pr = nt >> 1, od = nt & 1;
                    mma_f16(acc[mt][nt][0], acc[mt][nt][1],
                            acc[mt][nt][2], acc[mt][nt][3],
                            af[mt][0], af[mt][1], af[mt][2], af[mt][3],
                            bf[pr][od], bf[pr][od + 2]);
                }
        }
    }

    // ---------------- epilogue ----------------
    OT* Cb = C + bz * sC;
    #pragma unroll
    for (int mt = 0; mt < 4; mt++) {
        const long row0 = m0 + wm * 64 + mt * 16 + gid;
        #pragma unroll
        for (int nt = 0; nt < 4; nt++) {
            const long col = n0 + wn * 32 + nt * 8 + lq * 2;
            float v0 = acc[mt][nt][0], v1 = acc[mt][nt][1];
            float v2 = acc[mt][nt][2], v3 = acc[mt][nt][3];
            if (EPI == 0) { v0 *= alpha; v1 *= alpha; v2 *= alpha; v3 *= alpha; }
            if (EPI == 3 || EPI == 4) {
                float2 b2 = *(const float2*)(bias + col);
                v0 += b2.x; v1 += b2.y; v2 += b2.x; v3 += b2.y;
            }
            if (EPI == 3) {
                v0 = fmaxf(v0, 0.f); v1 = fmaxf(v1, 0.f);
                v2 = fmaxf(v2, 0.f); v3 = fmaxf(v3, 0.f);
            }
            const long o0 = row0 * (long)Ndim + col;
            const long o1 = (row0 + 8) * (long)Ndim + col;
            if (EPI == 2 || EPI == 4) {
                float2 r0 = *(const float2*)(R + o0);
                float2 r1 = *(const float2*)(R + o1);
                v0 += r0.x; v1 += r0.y; v2 += r1.x; v3 += r1.y;
            }
            if (sizeof(OT) == 4) {
                *(float2*)((float*)Cb + o0) = make_float2(v0, v1);
                *(float2*)((float*)Cb + o1) = make_float2(v2, v3);
            } else {
                *(__half2*)((__half*)Cb + o0) = __floats2half2_rn(v0, v1);
                *(__half2*)((__half*)Cb + o1) = __floats2half2_rn(v2, v3);
            }
        }
    }
}

// ---------------------------------------------------------------------------
// f32 -> f16 elementwise convert
// ---------------------------------------------------------------------------
__global__ __launch_bounds__(256)
void cvt16_k(const float* __restrict__ in, __half* __restrict__ out, long n4)
{
    long i = (long)blockIdx.x * 256 + threadIdx.x;
    if (i >= n4) return;
    float4 v = ((const float4*)in)[i];
    ((__half2*)out)[i * 2]     = __floats2half2_rn(v.x, v.y);
    ((__half2*)out)[i * 2 + 1] = __floats2half2_rn(v.z, v.w);
}

// ---------------------------------------------------------------------------
// Transpose per batch to fp16: xt16[b][m][s] = x[b][s][m]
// ---------------------------------------------------------------------------
__global__ __launch_bounds__(256)
void transpose16_k(const float* __restrict__ x, __half* __restrict__ xt)
{
    __shared__ float t[32][33];
    const int b  = blockIdx.z;
    const int bx = blockIdx.x * 32;
    const int by = blockIdx.y * 32;
    const float* xp = x  + (long)b * SMTOT;
    __half*      yp = xt + (long)b * SMTOT;
    const int txx = threadIdx.x, tyy = threadIdx.y;
    #pragma unroll
    for (int i = 0; i < 4; i++)
        t[tyy + i * 8][txx] = xp[(long)(by + tyy + i * 8) * MM + bx + txx];
    __syncthreads();
    #pragma unroll
    for (int i = 0; i < 4; i++)
        yp[(long)(bx + tyy + i * 8) * SS + by + txx] = __float2half(t[txx][tyy + i * 8]);
}

// ---------------------------------------------------------------------------
// Row softmax over 2048 columns, fp16 in / fp16 out, IN PLACE (one block/row)
// ---------------------------------------------------------------------------
__global__ __launch_bounds__(256)
void softmax16_k(__half* __restrict__ data)
{
    long row = blockIdx.x;
    __half2* p = (__half2*)(data + row * (long)SS);
    int t = threadIdx.x;
    float2 v[4];
    float mx = -INFINITY;
    #pragma unroll
    for (int i = 0; i < 4; i++) {
        __half2 h = p[t + i * 256];
        v[i] = __half22float2(h);
        mx = fmaxf(mx, fmaxf(v[i].x, v[i].y));
    }
    __shared__ float red[256];
    red[t] = mx; __syncthreads();
    for (int s = 128; s > 0; s >>= 1) {
        if (t < s) red[t] = fmaxf(red[t], red[t + s]);
        __syncthreads();
    }
    mx = red[0];
    __syncthreads();
    float sum = 0.f;
    #pragma unroll
    for (int i = 0; i < 4; i++) {
        v[i].x = __expf(v[i].x - mx);
        v[i].y = __expf(v[i].y - mx);
        sum += v[i].x + v[i].y;
    }
    red[t] = sum; __syncthreads();
    for (int s = 128; s > 0; s >>= 1) {
        if (t < s) red[t] += red[t + s];
        __syncthreads();
    }
    float inv = 1.f / red[0];
    #pragma unroll
    for (int i = 0; i < 4; i++)
        p[t + i * 256] = __floats2half2_rn(v[i].x * inv, v[i].y * inv);
}

// ---------------------------------------------------------------------------
// LayerNorm over full (S,M) plane per batch — deterministic 3-stage
// ---------------------------------------------------------------------------
__global__ __launch_bounds__(256)
void ln_reduce_k(const float* __restrict__ xx, float* __restrict__ part)
{
    int b = blockIdx.y;
    const float4* p = (const float4*)(xx + (long)b * SMTOT) + (long)blockIdx.x * 2048;
    float s = 0.f, q = 0.f;
    for (int i = threadIdx.x; i < 2048; i += 256) {
        float4 v = p[i];
        s += v.x + v.y + v.z + v.w;
        q += v.x * v.x + v.y * v.y + v.z * v.z + v.w * v.w;
    }
    __shared__ float rs[256], rq[256];
    rs[threadIdx.x] = s; rq[threadIdx.x] = q; __syncthreads();
    for (int st = 128; st > 0; st >>= 1) {
        if (threadIdx.x < st) {
            rs[threadIdx.x] += rs[threadIdx.x + st];
            rq[threadIdx.x] += rq[threadIdx.x + st];
        }
        __syncthreads();
    }
    if (threadIdx.x == 0) {
        int idx = (b * 256 + blockIdx.x) * 2;
        part[idx]     = rs[0];
        part[idx + 1] = rq[0];
    }
}

__global__ __launch_bounds__(256)
void ln_finalize_k(const float* __restrict__ part, float* __restrict__ stats)
{
    int b = blockIdx.x, t = threadIdx.x;
    float s = part[(b * 256 + t) * 2];
    float q = part[(b * 256 + t) * 2 + 1];
    __shared__ float rs[256], rq[256];
    rs[t] = s; rq[t] = q; __syncthreads();
    for (int st = 128; st > 0; st >>= 1) {
        if (t < st) { rs[t] += rs[t + st]; rq[t] += rq[t + st]; }
        __syncthreads();
    }
    if (t == 0) {
        float mean = rs[0] / (float)SMTOT;
        float var  = rq[0] / (float)SMTOT - mean * mean;
        stats[b * 2]     = mean;
        stats[b * 2 + 1] = rsqrtf(var + 1e-5f);
    }
}

template<bool WH>
__global__ __launch_bounds__(256)
void ln_apply_k(const float* __restrict__ xx, const float* __restrict__ w,
                const float* __restrict__ bbp, const float* __restrict__ stats,
                float* __restrict__ y, __half* __restrict__ y16)
{
    long i = (long)blockIdx.x * 256 + threadIdx.x;
    int b  = (int)(i / SM4);
    long sm = i - (long)b * SM4;
    float mean = stats[b * 2];
    float rstd = stats[b * 2 + 1];
    float4 v  = ((const float4*)xx)[i];
    float4 wv = ((const float4*)w)[sm];
    float4 bv = ((const float4*)bbp)[sm];
    float4 o;
    o.x = (v.x - mean) * rstd * wv.x + bv.x;
    o.y = (v.y - mean) * rstd * wv.y + bv.y;
    o.z = (v.z - mean) * rstd * wv.z + bv.z;
    o.w = (v.w - mean) * rstd * wv.w + bv.w;
    ((float4*)y)[i] = o;
    if (WH) {
        ((__half2*)y16)[i * 2]     = __floats2half2_rn(o.x, o.y);
        ((__half2*)y16)[i * 2 + 1] = __floats2half2_rn(o.z, o.w);
    }
}

// ---------------------------------------------------------------------------
// Launch
// ---------------------------------------------------------------------------
extern "C" void kernel_launch(void* const* d_in, const int* in_sizes, int n_in,
                              void* d_out, int out_size)
{
    const float* x     = (const float*)d_in[0];
    const float* w_out = (const float*)d_in[1];
    const float* ln1_w = (const float*)d_in[2];
    const float* ln1_b = (const float*)d_in[3];
    const float* w1    = (const float*)d_in[4];
    const float* b1    = (const float*)d_in[5];
    const float* w2    = (const float*)d_in[6];
    const float* b2    = (const float*)d_in[7];
    const float* ln2_w = (const float*)d_in[8];
    const float* ln2_b = (const float*)d_in[9];
    float* out = (float*)d_out;

    float  *pre1, *h, *pre2, *part, *stats;
    __half *x16, *xt16, *attn16, *ctx16, *h16, *ff116, *wout16, *w116, *w216;
    cudaGetSymbolAddress((void**)&pre1,   g_pre1);
    cudaGetSymbolAddress((void**)&h,      g_h);
    cudaGetSymbolAddress((void**)&pre2,   g_pre2);
    cudaGetSymbolAddress((void**)&part,   g_part);
    cudaGetSymbolAddress((void**)&stats,  g_stats);
    cudaGetSymbolAddress((void**)&x16,    g_x16);
    cudaGetSymbolAddress((void**)&xt16,   g_xt16);
    cudaGetSymbolAddress((void**)&attn16, g_attn16);
    cudaGetSymbolAddress((void**)&ctx16,  g_ctx16);
    cudaGetSymbolAddress((void**)&h16,    g_h16);
    cudaGetSymbolAddress((void**)&ff116,  g_ff116);
    cudaGetSymbolAddress((void**)&wout16, g_wout16);
    cudaGetSymbolAddress((void**)&w116,   g_w116);
    cudaGetSymbolAddress((void**)&w216,   g_w216);

    cudaFuncSetAttribute(gemm_h16<0, __half>, cudaFuncAttributeMaxDynamicSharedMemorySize, SMEM_TOT);
    cudaFuncSetAttribute(gemm_h16<1, __half>, cudaFuncAttributeMaxDynamicSharedMemorySize, SMEM_TOT);
    cudaFuncSetAttribute(gemm_h16<2, float>,  cudaFuncAttributeMaxDynamicSharedMemorySize, SMEM_TOT);
    cudaFuncSetAttribute(gemm_h16<3, __half>, cudaFuncAttributeMaxDynamicSharedMemorySize, SMEM_TOT);
    cudaFuncSetAttribute(gemm_h16<4, float>,  cudaFuncAttributeMaxDynamicSharedMemorySize, SMEM_TOT);

    dim3 blk(256);
    const float scale = 1.0f / 32.0f;   // 1/sqrt(1024)
    const long SSQ = (long)SS * SS;

    // 0. conversions (independent)
    cvt16_k<<<(unsigned)((BB * SMTOT / 4) / 256), blk>>>(x, x16, BB * SMTOT / 4);
    transpose16_k<<<dim3(MM / 32, SS / 32, BB), dim3(32, 8)>>>(x, xt16);
    cvt16_k<<<(unsigned)(((long)MM * MM / 4) / 256), blk>>>(w_out, wout16, (long)MM * MM / 4);
    cvt16_k<<<(unsigned)(((long)FF * MM / 4) / 256), blk>>>(w1, w116, (long)FF * MM / 4);
    cvt16_k<<<(unsigned)(((long)MM * FF / 4) / 256), blk>>>(w2, w216, (long)MM * FF / 4);

    // 1. scores16 = (x @ x^T) * scale    per-batch NT -> f16 into attn buffer
    gemm_h16<0, __half><<<dim3(SS / 128, SS / 128, BB), blk, SMEM_TOT>>>(
        x16, x16, attn16, nullptr, nullptr, MM, SS, SMTOT, SMTOT, SSQ, scale);

    // 2. softmax rows, in place on f16
    softmax16_k<<<(unsigned)(BB * SS), blk>>>(attn16);

    // 3. ctx16 = attn @ x                per-batch NT with B = xt16
    gemm_h16<1, __half><<<dim3(MM / 128, SS / 128, BB), blk, SMEM_TOT>>>(
        attn16, xt16, ctx16, nullptr, nullptr, SS, MM, SSQ, SMTOT, SMTOT, 1.f);

    // 4. pre1 = ctx @ w_out^T + x        folded: M=8192, N=1024, K=1024
    gemm_h16<2, float><<<dim3(MM / 128, (BB * SS) / 128, 1), blk, SMEM_TOT>>>(
        ctx16, wout16, pre1, nullptr, x, MM, MM, 0, 0, 0, 1.f);

    // 5. h = LN1(pre1), h16
    ln_reduce_k<<<dim3(256, BB), blk>>>(pre1, part);
    ln_finalize_k<<<BB, blk>>>(part, stats);
    ln_apply_k<true><<<(unsigned)((BB * SMTOT / 4) / 256), blk>>>(pre1, ln1_w, ln1_b, stats, h, h16);

    // 6. ff116 = relu(h @ w1^T + b1)     folded: M=8192, N=4096, K=1024
    gemm_h16<3, __half><<<dim3(FF / 128, (BB * SS) / 128, 1), blk, SMEM_TOT>>>(
        h16, w116, ff116, b1, nullptr, MM, FF, 0, 0, 0, 1.f);

    // 7. pre2 = ff1 @ w2^T + b2 + h      folded: M=8192, N=1024, K=4096
    gemm_h16<4, float><<<dim3(MM / 128, (BB * SS) / 128, 1), blk, SMEM_TOT>>>(
        ff116, w216, pre2, b2, h, FF, MM, 0, 0, 0, 1.f);

    // 8. out = LN2(pre2)
    ln_reduce_k<<<dim3(256, BB), blk>>>(pre2, part);
    ln_finalize_k<<<BB, blk>>>(part, stats);
    ln_apply_k<false><<<(unsigned)((BB * SMTOT / 4) / 256), blk>>>(pre2, ln2_w, ln2_b, stats, out, nullptr);
}